// round 9
// baseline (speedup 1.0000x reference)
#include <cuda_runtime.h>
#include <cuda_fp16.h>
#include <cstdint>
#include <math.h>

#define B_    32
#define C_    64
#define HW_   64
#define NTILE 16

// ---- smem layout ----
#define XS_STRIDE  80                        // bytes per (R,px) row: 64 int8 + 16 pad
#define XS_BYTES   (6*66*XS_STRIDE)          // 31680
#define QBUF_OFF   XS_BYTES
#define QPX        132                       // padded px stride (floats)
#define QBUF_BYTES (4*64*QPX*4)              // 135168
#define SMEM_TOTAL (QBUF_OFF + QBUF_BYTES)   // 166848

#define XQ_SCALE   (127.0f / 6.0f)

// int8 B-fragment table: [warpclass 8][frag 32 = (kt*4+j)*4... indexed (kt,j,ng)][lane 32]
__device__ uint2 g_wfragB8[8][32][32];
__device__ float g_dq_scale;                 // (6/127) * (maxw/127)
__device__ float g_part[B_][C_][NTILE];

__device__ __forceinline__ void mma_s8(int4& c, const uint4 a, const uint2 b) {
    asm volatile("mma.sync.aligned.m16n8k32.row.col.s32.s8.s8.s32 "
        "{%0,%1,%2,%3}, {%4,%5,%6,%7}, {%8,%9}, {%0,%1,%2,%3};"
        : "+r"(c.x), "+r"(c.y), "+r"(c.z), "+r"(c.w)
        : "r"(a.x), "r"(a.y), "r"(a.z), "r"(a.w), "r"(b.x), "r"(b.y));
}
__device__ __forceinline__ void ldsm_x4(uint4& d, uint32_t addr) {
    asm volatile("ldmatrix.sync.aligned.m8n8.x4.shared.b16 {%0,%1,%2,%3}, [%4];"
        : "=r"(d.x), "=r"(d.y), "=r"(d.z), "=r"(d.w) : "r"(addr));
}
__device__ __forceinline__ uint32_t smem_u32(const void* p) {
    uint32_t a;
    asm("{ .reg .u64 t; cvta.to.shared.u64 t, %1; cvt.u32.u64 %0, t; }" : "=r"(a) : "l"(p));
    return a;
}
__device__ __forceinline__ int q8(float v, float s) {
    int i = __float2int_rn(fminf(fmaxf(v * s, -127.f), 127.f));
    return i;
}

// ---- prep: exact max|w| (deterministic), then int8 fragment table ----
__global__ void prep_int8(const float* __restrict__ w) {
    __shared__ float smax[256];
    __shared__ float s_step;
    const int tid = threadIdx.x;

    float m = 0.f;
    for (int i = tid; i < 65536; i += 256) m = fmaxf(m, fabsf(w[i]));
    smax[tid] = m;
    __syncthreads();
    for (int s = 128; s > 0; s >>= 1) {
        if (tid < s) smax[tid] = fmaxf(smax[tid], smax[tid + s]);
        __syncthreads();
    }
    if (tid == 0) {
        float step = smax[0] / 127.f;
        if (step <= 0.f) step = 1.f;
        s_step = step;
        g_dq_scale = (6.f / 127.f) * step;
    }
    __syncthreads();
    const float inv_step = 1.f / s_step;

    // fragment table: 8 wc * 32 frag * 32 lane
    for (int idx = tid; idx < 8 * 32 * 32; idx += 256) {
        int wc = idx >> 10, f = (idx >> 5) & 31, t = idx & 31;
        int q = wc >> 1, h = wc & 1;
        int kt = f >> 4, j = (f >> 2) & 3, ng = f & 3;
        int jh = j >> 1, jw = j & 1;
        int a = q >> 1, bb = q & 1;
        int kh = a ? (jh ? 2 : 0) : (jh ? 3 : 1);
        int kw = bb ? (jw ? 2 : 0) : (jw ? 3 : 1);
        int tap = kh * 4 + kw;
        int oc  = h * 32 + ng * 8 + (t >> 2);
        int k0  = kt * 32 + (t & 3) * 4;
        uint32_t b0 = 0, b1 = 0;
        #pragma unroll
        for (int e = 0; e < 4; e++) {
            int v0 = q8(w[(k0 + e) * 1024 + oc * 16 + tap], inv_step);
            int v1 = q8(w[(k0 + 16 + e) * 1024 + oc * 16 + tap], inv_step);
            b0 |= ((uint32_t)(v0 & 0xFF)) << (8 * e);
            b1 |= ((uint32_t)(v1 & 0xFF)) << (8 * e);
        }
        g_wfragB8[wc][f][t] = make_uint2(b0, b1);
    }
}

// ---- main fused kernel ----
__global__ void __launch_bounds__(256, 1)
fused_imma_kernel(const float* __restrict__ x, const float* __restrict__ bias)
{
    extern __shared__ char smem[];
    char*  xs   = smem;                                  // [6*66][80] int8
    float* qbuf = (float*)(smem + QBUF_OFF);             // [4q][64oc][132px]
    const uint32_t xs_b = smem_u32(smem);

    const int tid  = threadIdx.x;
    const int lane = tid & 31;
    const int wid  = tid >> 5;
    const int tile = blockIdx.x;
    const int b    = blockIdx.y;
    const int pr0  = tile * 4;

    // ---- load B-fragments (int8 weights): 32 uint2 = 64 regs ----
    uint2 Bw[32];
    #pragma unroll
    for (int f = 0; f < 32; f++) Bw[f] = g_wfragB8[wid][f][lane];
    const float dqs = g_dq_scale;

    // ---- stage x slab as int8 [R][px][ic], clamp +-6, zero borders ----
    const float* xb = x + (size_t)b * C_ * HW_ * HW_;
    for (int ri = tid; ri < 384; ri += 256) {            // 6 rows * 64 ic
        int R = ri >> 6, ic = ri & 63, ih = pr0 - 1 + R;
        signed char hv[66];
        #pragma unroll
        for (int p = 0; p < 66; p++) hv[p] = 0;
        if (ih >= 0 && ih < HW_) {
            const float4* src = (const float4*)(xb + ((size_t)ic * HW_ + ih) * HW_);
            #pragma unroll
            for (int p = 0; p < 16; p++) {
                float4 v = src[p];
                hv[1 + 4*p] = (signed char)q8(v.x, XQ_SCALE);
                hv[2 + 4*p] = (signed char)q8(v.y, XQ_SCALE);
                hv[3 + 4*p] = (signed char)q8(v.z, XQ_SCALE);
                hv[4 + 4*p] = (signed char)q8(v.w, XQ_SCALE);
            }
        }
        #pragma unroll
        for (int p = 0; p < 66; p++)
            xs[(R * 66 + p) * XS_STRIDE + ic] = hv[p];
    }
    __syncthreads();

    const int q = wid >> 1, h = wid & 1;
    const int a = q >> 1, bb = q & 1;
    const int ro[2] = { a ? 2 : 1, a ? 1 : 0 };          // jh = 0,1
    const int co[2] = { bb ? 2 : 1, bb ? 1 : 0 };        // jw = 0,1

    // ldmatrix lane decomposition (b16 view of int8 rows)
    const int mblk = (lane >> 3) & 1;                    // +8 px rows
    const int kblk = lane >> 4;                          // +16B ic chunk
    const int lrow = lane & 7;

    float bb8[8], psum8[8];
    #pragma unroll
    for (int ol = 0; ol < 8; ol++) { bb8[ol] = bias[wid * 8 + ol]; psum8[ol] = 0.f; }

    for (int hf = 0; hf < 2; hf++) {
        #pragma unroll 2
        for (int nt = 0; nt < 8; nt++) {
            const int lr  = hf * 2 + (nt >> 2);
            const int pc0 = (nt & 3) * 16;

            // A fragments: x tiles [j][kt], kt covers 32 ic each
            uint4 Af[4][2];
            #pragma unroll
            for (int j = 0; j < 4; j++) {
                int R  = lr + ro[j >> 1];
                int px = pc0 + co[j & 1] + mblk * 8 + lrow;
                uint32_t rowbase = xs_b + (R * 66 + px) * XS_STRIDE + kblk * 16;
                ldsm_x4(Af[j][0], rowbase);
                ldsm_x4(Af[j][1], rowbase + 32);
            }

            int4 acc[4];
            #pragma unroll
            for (int ng = 0; ng < 4; ng++) acc[ng] = make_int4(0, 0, 0, 0);

            #pragma unroll
            for (int kt = 0; kt < 2; kt++)
                #pragma unroll
                for (int j = 0; j < 4; j++)
                    #pragma unroll
                    for (int ng = 0; ng < 4; ng++)
                        mma_s8(acc[ng], Af[j][kt], Bw[(kt * 4 + j) * 4 + ng]);

            // store (dequant): c0,c1 = (px=t/4, oc=2(t%4),+1); c2,c3 at px+8
            int pxh = (nt >> 2) * 64 + pc0 + (lane >> 2);
            int ocb = h * 32 + 2 * (lane & 3);
            #pragma unroll
            for (int ng = 0; ng < 4; ng++) {
                float* d = qbuf + (q * 64 + ocb + ng * 8) * QPX + pxh;
                d[0]       = dqs * (float)acc[ng].x;
                d[QPX]     = dqs * (float)acc[ng].y;
                d[8]       = dqs * (float)acc[ng].z;
                d[QPX + 8] = dqs * (float)acc[ng].w;
            }
        }
        __syncthreads();

        // ---- epilogue: warp w owns oc rows w*8..w*8+7; lane reads px lane*4..+3 ----
        #pragma unroll
        for (int ol = 0; ol < 8; ol++) {
            int oc = wid * 8 + ol;
            const float* base = qbuf + oc * QPX + lane * 4;
            float4 v0 = *(const float4*)(base + 0 * 64 * QPX);
            float4 v1 = *(const float4*)(base + 1 * 64 * QPX);
            float4 v2 = *(const float4*)(base + 2 * 64 * QPX);
            float4 v3 = *(const float4*)(base + 3 * 64 * QPX);
            float m, s = 0.f;
            m = fmaxf(fmaxf(v0.x, v1.x), fmaxf(v2.x, v3.x)) + bb8[ol];
            s += fminf(fmaxf(m, -1.f), 1.f);
            m = fmaxf(fmaxf(v0.y, v1.y), fmaxf(v2.y, v3.y)) + bb8[ol];
            s += fminf(fmaxf(m, -1.f), 1.f);
            m = fmaxf(fmaxf(v0.z, v1.z), fmaxf(v2.z, v3.z)) + bb8[ol];
            s += fminf(fmaxf(m, -1.f), 1.f);
            m = fmaxf(fmaxf(v0.w, v1.w), fmaxf(v2.w, v3.w)) + bb8[ol];
            s += fminf(fmaxf(m, -1.f), 1.f);
            psum8[ol] += s;
        }
        __syncthreads();
    }

    // ---- reduction: reuse qbuf as scratch [64 oc][32 lanes] ----
    float* red2 = qbuf;
    #pragma unroll
    for (int ol = 0; ol < 8; ol++)
        red2[(wid * 8 + ol) * 32 + lane] = psum8[ol];
    __syncthreads();
    if (tid < 64) {
        const float4* r = (const float4*)(red2 + tid * 32);
        float4 s4 = make_float4(0.f, 0.f, 0.f, 0.f);
        #pragma unroll
        for (int k = 0; k < 8; k++) {
            float4 v = r[k];
            s4.x += v.x; s4.y += v.y; s4.z += v.z; s4.w += v.w;
        }
        g_part[b][tid][tile] = (s4.x + s4.y) + (s4.z + s4.w);
    }
}

__global__ void finalize_kernel(float* __restrict__ out)
{
    int b  = blockIdx.x;
    int oc = threadIdx.x;
    float s = 0.f;
    #pragma unroll
    for (int t = 0; t < NTILE; ++t) s += g_part[b][oc][t];
    out[b * C_ + oc] = tanhf(s * (1.0f / 4096.0f));
}

extern "C" void kernel_launch(void* const* d_in, const int* in_sizes, int n_in,
                              void* d_out, int out_size)
{
    const float* x    = (const float*)d_in[0];
    const float* w    = (const float*)d_in[1];
    const float* bias = (const float*)d_in[2];
    float* out = (float*)d_out;

    cudaFuncSetAttribute(fused_imma_kernel,
                         cudaFuncAttributeMaxDynamicSharedMemorySize, SMEM_TOTAL);

    prep_int8<<<1, 256>>>(w);
    fused_imma_kernel<<<dim3(NTILE, B_), 256, SMEM_TOTAL>>>(x, bias);
    finalize_kernel<<<B_, C_>>>(out);
}

// round 10
// speedup vs baseline: 2.4956x; 2.4956x over previous
#include <cuda_runtime.h>
#include <cuda_fp16.h>
#include <cstdint>
#include <math.h>

#define B_    32
#define C_    64
#define HW_   64
#define NTILE 16

// ---- smem layout ----
#define XS_HSTRIDE 72                        // halves per (R,px) row (144B)
#define XS_BYTES   (6*66*XS_HSTRIDE*2)       // 57024
#define QBUF_OFF   XS_BYTES
#define QPX        132                       // padded px stride (floats)
#define QBUF_BYTES (4*64*QPX*4)              // 135168
#define SMEM_TOTAL (QBUF_OFF + QBUF_BYTES)   // 192192

// fragment-ordered B (weight) table: [warpclass 8][frag 64 = (kt*4+j)*4+ng][lane 32]
__device__ uint2 g_wfragB[8][64][32];
__device__ float g_part[B_][C_][NTILE];
__device__ int   g_count[B_];                // zero-init; self-resets each run

__device__ __forceinline__ void mma_xw(float* c, const uint4 a, const uint2 b) {
    asm volatile("mma.sync.aligned.m16n8k16.row.col.f32.f16.f16.f32 "
        "{%0,%1,%2,%3}, {%4,%5,%6,%7}, {%8,%9}, {%0,%1,%2,%3};"
        : "+f"(c[0]), "+f"(c[1]), "+f"(c[2]), "+f"(c[3])
        : "r"(a.x), "r"(a.y), "r"(a.z), "r"(a.w), "r"(b.x), "r"(b.y));
}
__device__ __forceinline__ void ldsm_x4(uint4& d, uint32_t addr) {
    asm volatile("ldmatrix.sync.aligned.m8n8.x4.shared.b16 {%0,%1,%2,%3}, [%4];"
        : "=r"(d.x), "=r"(d.y), "=r"(d.z), "=r"(d.w) : "r"(addr));
}
__device__ __forceinline__ uint32_t smem_u32(const void* p) {
    uint32_t a;
    asm("{ .reg .u64 t; cvta.to.shared.u64 t, %1; cvt.u32.u64 %0, t; }" : "=r"(a) : "l"(p));
    return a;
}

// ---- prep: w[ic][oc][kh][kw] fp32 -> B-fragment fp16 table ----
__global__ void prep_wfragB(const float* __restrict__ w) {
    int idx = blockIdx.x * 256 + threadIdx.x;            // 8*64*32 = 16384
    if (idx >= 16384) return;
    int wc = idx >> 11, f = (idx >> 5) & 63, t = idx & 31;
    int q = wc >> 1, h = wc & 1;
    int kt = f >> 4, j = (f >> 2) & 3, ng = f & 3;
    int jh = j >> 1, jw = j & 1;
    int a = q >> 1, bb = q & 1;
    int kh = a ? (jh ? 2 : 0) : (jh ? 3 : 1);
    int kw = bb ? (jw ? 2 : 0) : (jw ? 3 : 1);
    int tap = kh * 4 + kw;
    int oc = h * 32 + ng * 8 + (t >> 2);
    int k0 = kt * 16 + (t & 3) * 2;
    uint2 v;
    __half2 b0 = __floats2half2_rn(w[k0 * 1024 + oc * 16 + tap],
                                   w[(k0 + 1) * 1024 + oc * 16 + tap]);
    __half2 b1 = __floats2half2_rn(w[(k0 + 8) * 1024 + oc * 16 + tap],
                                   w[(k0 + 9) * 1024 + oc * 16 + tap]);
    v.x = *(uint32_t*)&b0;
    v.y = *(uint32_t*)&b1;
    g_wfragB[wc][f][t] = v;
}

// ---- main fused kernel (includes final per-batch reduction) ----
__global__ void __launch_bounds__(256, 1)
fused_hmma_kernel(const float* __restrict__ x, const float* __restrict__ bias,
                  float* __restrict__ out)
{
    extern __shared__ char smem[];
    __half* xs   = (__half*)smem;                        // [6*66][72]
    float*  qbuf = (float*)(smem + QBUF_OFF);            // [4q][64oc][132px]
    __shared__ int s_last;
    const uint32_t xs_b = smem_u32(smem);

    const int tid  = threadIdx.x;
    const int lane = tid & 31;
    const int wid  = tid >> 5;
    const int tile = blockIdx.x;
    const int b    = blockIdx.y;
    const int pr0  = tile * 4;

    // ---- load B-fragments (weights) into registers: 64 uint2 = 128 regs ----
    uint2 Bw[64];
    #pragma unroll
    for (int f = 0; f < 64; f++) Bw[f] = g_wfragB[wid][f][lane];

    // ---- stage x slab as fp16 [R][px][ic], zero-padded borders ----
    const float* xb = x + (size_t)b * C_ * HW_ * HW_;
    for (int ri = tid; ri < 384; ri += 256) {            // 6 rows * 64 ic
        int R = ri >> 6, ic = ri & 63, ih = pr0 - 1 + R;
        __half hv[66];
        #pragma unroll
        for (int p = 0; p < 66; p++) hv[p] = __float2half(0.f);
        if (ih >= 0 && ih < HW_) {
            const float4* src = (const float4*)(xb + ((size_t)ic * HW_ + ih) * HW_);
            #pragma unroll
            for (int p = 0; p < 16; p++) {
                float4 v = src[p];
                hv[1 + 4*p] = __float2half(v.x);
                hv[2 + 4*p] = __float2half(v.y);
                hv[3 + 4*p] = __float2half(v.z);
                hv[4 + 4*p] = __float2half(v.w);
            }
        }
        #pragma unroll
        for (int p = 0; p < 66; p++)
            xs[(R * 66 + p) * XS_HSTRIDE + ic] = hv[p];
    }
    __syncthreads();

    const int q = wid >> 1, h = wid & 1;
    const int a = q >> 1, bb = q & 1;
    const int ro[2] = { a ? 2 : 1, a ? 1 : 0 };          // jh = 0,1
    const int co[2] = { bb ? 2 : 1, bb ? 1 : 0 };        // jw = 0,1

    // per-lane invariant ldmatrix offset parts
    const int mblk = (lane >> 3) & 1;
    const int kblk = lane >> 4;
    const int lrow = lane & 7;

    float bb8[8], psum8[8];
    #pragma unroll
    for (int ol = 0; ol < 8; ol++) { bb8[ol] = bias[wid * 8 + ol]; psum8[ol] = 0.f; }

    for (int hf = 0; hf < 2; hf++) {
        // ---- mainloop: 8 n-tiles of 16 px covering 2 pooled rows x 64 px ----
        #pragma unroll 2
        for (int nt = 0; nt < 8; nt++) {
            const int lr  = hf * 2 + (nt >> 2);
            const int pc0 = (nt & 3) * 16;

            // A fragments: x tiles, [j][kt]
            uint4 Af[4][4];
            #pragma unroll
            for (int j = 0; j < 4; j++) {
                int R  = lr + ro[j >> 1];
                int px = pc0 + co[j & 1] + mblk * 8 + lrow;
                uint32_t rowbase = xs_b +
                    (((R * 66 + px) * XS_HSTRIDE) + kblk * 8) * 2;
                #pragma unroll
                for (int kt = 0; kt < 4; kt++)
                    ldsm_x4(Af[j][kt], rowbase + kt * 32);
            }

            float acc[4][4];
            #pragma unroll
            for (int ng = 0; ng < 4; ng++)
                #pragma unroll
                for (int i = 0; i < 4; i++) acc[ng][i] = 0.f;

            #pragma unroll
            for (int kt = 0; kt < 4; kt++)
                #pragma unroll
                for (int j = 0; j < 4; j++)
                    #pragma unroll
                    for (int ng = 0; ng < 4; ng++)
                        mma_xw(acc[ng], Af[j][kt], Bw[(kt * 4 + j) * 4 + ng]);

            // store: c0 = (px = t/4, oc = ng*8 + 2(t%4)), c1 = oc+1, c2/c3 = px+8
            int pxh = (nt >> 2) * 64 + pc0 + (lane >> 2);
            int ocb = h * 32 + 2 * (lane & 3);
            #pragma unroll
            for (int ng = 0; ng < 4; ng++) {
                float* d = qbuf + (q * 64 + ocb + ng * 8) * QPX + pxh;
                d[0]           = acc[ng][0];
                d[QPX]         = acc[ng][1];
                d[8]           = acc[ng][2];
                d[QPX + 8]     = acc[ng][3];
            }
        }
        __syncthreads();

        // ---- epilogue: warp w owns oc rows w*8..w*8+7; lane reads px lane*4..+3 ----
        #pragma unroll
        for (int ol = 0; ol < 8; ol++) {
            int oc = wid * 8 + ol;
            const float* base = qbuf + oc * QPX + lane * 4;
            float4 v0 = *(const float4*)(base + 0 * 64 * QPX);
            float4 v1 = *(const float4*)(base + 1 * 64 * QPX);
            float4 v2 = *(const float4*)(base + 2 * 64 * QPX);
            float4 v3 = *(const float4*)(base + 3 * 64 * QPX);
            float m, s = 0.f;
            m = fmaxf(fmaxf(v0.x, v1.x), fmaxf(v2.x, v3.x)) + bb8[ol];
            s += fminf(fmaxf(m, -1.f), 1.f);
            m = fmaxf(fmaxf(v0.y, v1.y), fmaxf(v2.y, v3.y)) + bb8[ol];
            s += fminf(fmaxf(m, -1.f), 1.f);
            m = fmaxf(fmaxf(v0.z, v1.z), fmaxf(v2.z, v3.z)) + bb8[ol];
            s += fminf(fmaxf(m, -1.f), 1.f);
            m = fmaxf(fmaxf(v0.w, v1.w), fmaxf(v2.w, v3.w)) + bb8[ol];
            s += fminf(fmaxf(m, -1.f), 1.f);
            psum8[ol] += s;
        }
        __syncthreads();
    }

    // ---- reduction: reuse qbuf as scratch [64 oc][32 lanes] ----
    float* red2 = qbuf;
    #pragma unroll
    for (int ol = 0; ol < 8; ol++)
        red2[(wid * 8 + ol) * 32 + lane] = psum8[ol];
    __syncthreads();
    if (tid < 64) {
        const float4* r = (const float4*)(red2 + tid * 32);
        float4 s4 = make_float4(0.f, 0.f, 0.f, 0.f);
        #pragma unroll
        for (int k = 0; k < 8; k++) {
            float4 v = r[k];
            s4.x += v.x; s4.y += v.y; s4.z += v.z; s4.w += v.w;
        }
        g_part[b][tid][tile] = (s4.x + s4.y) + (s4.z + s4.w);
    }

    // ---- last CTA of this batch finalizes (deterministic: fixed-order sum) ----
    __threadfence();
    __syncthreads();
    if (tid == 0) {
        int c = atomicAdd(&g_count[b], 1);
        s_last = (c == NTILE - 1);
    }
    __syncthreads();
    if (s_last) {
        __threadfence();
        if (tid < 64) {
            float s = 0.f;
            #pragma unroll
            for (int t = 0; t < NTILE; ++t) s += g_part[b][tid][t];
            out[b * C_ + tid] = tanhf(s * (1.0f / 4096.0f));
        }
        if (tid == 0) g_count[b] = 0;        // reset for next graph replay
    }
}

extern "C" void kernel_launch(void* const* d_in, const int* in_sizes, int n_in,
                              void* d_out, int out_size)
{
    const float* x    = (const float*)d_in[0];
    const float* w    = (const float*)d_in[1];
    const float* bias = (const float*)d_in[2];
    float* out = (float*)d_out;

    cudaFuncSetAttribute(fused_hmma_kernel,
                         cudaFuncAttributeMaxDynamicSharedMemorySize, SMEM_TOTAL);

    prep_wfragB<<<64, 256>>>(w);
    fused_hmma_kernel<<<dim3(NTILE, B_), 256, SMEM_TOTAL>>>(x, bias, out);
}

// round 11
// speedup vs baseline: 2.5483x; 1.0211x over previous
#include <cuda_runtime.h>
#include <cuda_fp16.h>
#include <cstdint>
#include <math.h>

#define B_    32
#define C_    64
#define HW_   64
#define NTILE 16

// ---- smem layout (bytes) ----
#define XS_HSTRIDE 72                         // halves per (R,px) row (144B)
#define XS_BYTES   (6*66*XS_HSTRIDE*2)        // 57024
#define QB_OFF     XS_BYTES
#define QOC        72                         // padded oc stride (halves, 144B)
#define QB_BYTES   (2*4*64*QOC*2)             // 73728  [ktg][q][px64][oc72] fp16
#define BIAS_OFF   (QB_OFF + QB_BYTES)        // 130752
#define RED_OFF    (BIAS_OFF + 256)           // 131008
#define REDPX      65
#define RED_BYTES  (64*REDPX*4)               // 16640
#define RED2_OFF   (RED_OFF + RED_BYTES)      // 147648
#define SMEM_TOTAL (RED2_OFF + 64*8*4)        // 149696

// fragment-ordered B (weight) table: [warpclass 8][frag 64 = (kt*4+j)*4+ng][lane 32]
__device__ uint2 g_wfragB[8][64][32];
__device__ float g_part[B_][C_][NTILE];

__device__ __forceinline__ void mma_xw(float* c, const uint4 a, const uint2 b) {
    asm volatile("mma.sync.aligned.m16n8k16.row.col.f32.f16.f16.f32 "
        "{%0,%1,%2,%3}, {%4,%5,%6,%7}, {%8,%9}, {%0,%1,%2,%3};"
        : "+f"(c[0]), "+f"(c[1]), "+f"(c[2]), "+f"(c[3])
        : "r"(a.x), "r"(a.y), "r"(a.z), "r"(a.w), "r"(b.x), "r"(b.y));
}
__device__ __forceinline__ void ldsm_x4(uint4& d, uint32_t addr) {
    asm volatile("ldmatrix.sync.aligned.m8n8.x4.shared.b16 {%0,%1,%2,%3}, [%4];"
        : "=r"(d.x), "=r"(d.y), "=r"(d.z), "=r"(d.w) : "r"(addr));
}
__device__ __forceinline__ uint32_t smem_u32(const void* p) {
    uint32_t a;
    asm("{ .reg .u64 t; cvta.to.shared.u64 t, %1; cvt.u32.u64 %0, t; }" : "=r"(a) : "l"(p));
    return a;
}
__device__ __forceinline__ uint32_t pack_h2(float lo, float hi) {
    __half2 h = __floats2half2_rn(lo, hi);
    return *(uint32_t*)&h;
}

// ---- prep: w[ic][oc][kh][kw] fp32 -> B-fragment fp16 table ----
__global__ void prep_wfragB(const float* __restrict__ w) {
    int idx = blockIdx.x * 256 + threadIdx.x;            // 8*64*32 = 16384
    if (idx >= 16384) return;
    int wc = idx >> 11, f = (idx >> 5) & 63, t = idx & 31;
    int q = wc >> 1, h = wc & 1;
    int kt = f >> 4, j = (f >> 2) & 3, ng = f & 3;
    int jh = j >> 1, jw = j & 1;
    int a = q >> 1, bb = q & 1;
    int kh = a ? (jh ? 2 : 0) : (jh ? 3 : 1);
    int kw = bb ? (jw ? 2 : 0) : (jw ? 3 : 1);
    int tap = kh * 4 + kw;
    int oc = h * 32 + ng * 8 + (t >> 2);
    int k0 = kt * 16 + (t & 3) * 2;
    uint2 v;
    __half2 b0 = __floats2half2_rn(w[k0 * 1024 + oc * 16 + tap],
                                   w[(k0 + 1) * 1024 + oc * 16 + tap]);
    __half2 b1 = __floats2half2_rn(w[(k0 + 8) * 1024 + oc * 16 + tap],
                                   w[(k0 + 9) * 1024 + oc * 16 + tap]);
    v.x = *(uint32_t*)&b0;
    v.y = *(uint32_t*)&b1;
    g_wfragB[wc][f][t] = v;
}

// ---- main fused kernel: 512 threads, kt split across warp pairs ----
__global__ void __launch_bounds__(512, 1)
fused_hmma_kernel(const float* __restrict__ x, const float* __restrict__ bias)
{
    extern __shared__ char smem[];
    __half* xs    = (__half*)smem;                       // [6*66][72]
    __half* qbuf  = (__half*)(smem + QB_OFF);            // [2ktg][4q][64px][72oc]
    float*  biass = (float*)(smem + BIAS_OFF);           // [64]
    float*  red   = (float*)(smem + RED_OFF);            // [64oc][65px]
    float*  red2  = (float*)(smem + RED2_OFF);           // [64oc][8]
    const uint32_t xs_b = smem_u32(smem);

    const int tid  = threadIdx.x;
    const int lane = tid & 31;
    const int wid  = tid >> 5;                           // 0..15
    const int wc   = wid & 7;                            // warpclass (q,h)
    const int ktg  = wid >> 3;                           // kt group 0/1
    const int tile = blockIdx.x;
    const int b    = blockIdx.y;
    const int pr0  = tile * 4;

    // ---- load this warp's half of the B-fragments: 32 uint2 = 64 regs ----
    uint2 Bw[32];
    #pragma unroll
    for (int f = 0; f < 32; f++) Bw[f] = g_wfragB[wc][ktg * 32 + f][lane];

    // ---- stage x slab as fp16 [R][px][ic], zero-padded borders ----
    const float* xb = x + (size_t)b * C_ * HW_ * HW_;
    if (tid < 384) {
        int R = tid >> 6, ic = tid & 63, ih = pr0 - 1 + R;
        __half hv[66];
        #pragma unroll
        for (int p = 0; p < 66; p++) hv[p] = __float2half(0.f);
        if (ih >= 0 && ih < HW_) {
            const float4* src = (const float4*)(xb + ((size_t)ic * HW_ + ih) * HW_);
            #pragma unroll
            for (int p = 0; p < 16; p++) {
                float4 v = src[p];
                hv[1 + 4*p] = __float2half(v.x);
                hv[2 + 4*p] = __float2half(v.y);
                hv[3 + 4*p] = __float2half(v.z);
                hv[4 + 4*p] = __float2half(v.w);
            }
        }
        #pragma unroll
        for (int p = 0; p < 66; p++)
            xs[(R * 66 + p) * XS_HSTRIDE + ic] = hv[p];
    }
    if (tid < 64) biass[tid] = bias[tid];
    __syncthreads();

    const int q = wc >> 1, h = wc & 1;
    const int a = q >> 1, bb = q & 1;
    const int ro[2] = { a ? 2 : 1, a ? 1 : 0 };          // jh = 0,1
    const int co[2] = { bb ? 2 : 1, bb ? 1 : 0 };        // jw = 0,1

    const int mblk = (lane >> 3) & 1;
    const int kblk = lane >> 4;
    const int lrow = lane & 7;

    // epilogue coords
    const int epx  = tid >> 3;                           // 0..63
    const int eoc8 = (tid & 7) * 8;

    float psum[8];
    #pragma unroll
    for (int e = 0; e < 8; e++) psum[e] = 0.f;

    for (int r = 0; r < 4; r++) {                        // one pooled row per round
        // ---- mainloop: 4 n-tiles of 16 px ----
        #pragma unroll
        for (int nt = 0; nt < 4; nt++) {
            const int pc0 = nt * 16;

            uint4 Af[4][2];
            #pragma unroll
            for (int j = 0; j < 4; j++) {
                int R  = r + ro[j >> 1];
                int px = pc0 + co[j & 1] + mblk * 8 + lrow;
                uint32_t rowbase = xs_b +
                    (((R * 66 + px) * XS_HSTRIDE) + kblk * 8) * 2;
                #pragma unroll
                for (int ktl = 0; ktl < 2; ktl++)
                    ldsm_x4(Af[j][ktl], rowbase + (ktg * 2 + ktl) * 32);
            }

            float acc[4][4];
            #pragma unroll
            for (int ng = 0; ng < 4; ng++)
                #pragma unroll
                for (int i = 0; i < 4; i++) acc[ng][i] = 0.f;

            #pragma unroll
            for (int ktl = 0; ktl < 2; ktl++)
                #pragma unroll
                for (int j = 0; j < 4; j++)
                    #pragma unroll
                    for (int ng = 0; ng < 4; ng++)
                        mma_xw(acc[ng], Af[j][ktl], Bw[(ktl * 4 + j) * 4 + ng]);

            // store fp16 pairs: c0,c1 -> (px=pc0+g, oc=ocb,ocb+1); c2,c3 -> px+8
            int pxl = pc0 + (lane >> 2);
            int ocb = h * 32 + 2 * (lane & 3);
            __half* qb = qbuf + ((size_t)(ktg * 4 + q) * 64) * QOC;
            #pragma unroll
            for (int ng = 0; ng < 4; ng++) {
                *(uint32_t*)&qb[(pxl)     * QOC + ocb + ng * 8] = pack_h2(acc[ng][0], acc[ng][1]);
                *(uint32_t*)&qb[(pxl + 8) * QOC + ocb + ng * 8] = pack_h2(acc[ng][2], acc[ng][3]);
            }
        }
        __syncthreads();

        // ---- epilogue: thread = (px, 8 oc); sum ktg halves, max over q, clip ----
        {
            float mx[8];
            #pragma unroll
            for (int e = 0; e < 8; e++) mx[e] = -1e30f;
            #pragma unroll
            for (int qq = 0; qq < 4; qq++) {
                uint4 u0 = *(const uint4*)&qbuf[((size_t)(qq)     * 64 + epx) * QOC + eoc8];
                uint4 u1 = *(const uint4*)&qbuf[((size_t)(4 + qq) * 64 + epx) * QOC + eoc8];
                const uint32_t* p0 = (const uint32_t*)&u0;
                const uint32_t* p1 = (const uint32_t*)&u1;
                #pragma unroll
                for (int d = 0; d < 4; d++) {
                    float2 f0 = __half22float2(*(__half2*)&p0[d]);
                    float2 f1 = __half22float2(*(__half2*)&p1[d]);
                    float y0 = f0.x + f1.x;
                    float y1 = f0.y + f1.y;
                    mx[d * 2]     = fmaxf(mx[d * 2], y0);
                    mx[d * 2 + 1] = fmaxf(mx[d * 2 + 1], y1);
                }
            }
            #pragma unroll
            for (int e = 0; e < 8; e++) {
                float m = mx[e] + biass[eoc8 + e];
                psum[e] += fminf(fmaxf(m, -1.f), 1.f);
            }
        }
        __syncthreads();
    }

    // ---- per-tile reduction (deterministic) ----
    #pragma unroll
    for (int e = 0; e < 8; e++)
        red[(eoc8 + e) * REDPX + epx] = psum[e];
    __syncthreads();
    {
        int oc = tid >> 3, ch = tid & 7;
        const float* rr = red + oc * REDPX + ch * 8;
        float v = ((rr[0] + rr[1]) + (rr[2] + rr[3]))
                + ((rr[4] + rr[5]) + (rr[6] + rr[7]));
        red2[oc * 8 + ch] = v;
    }
    __syncthreads();
    if (tid < 64) {
        const float* rr = red2 + tid * 8;
        float v = ((rr[0] + rr[1]) + (rr[2] + rr[3]))
                + ((rr[4] + rr[5]) + (rr[6] + rr[7]));
        g_part[b][tid][tile] = v;
    }
}

__global__ void finalize_kernel(float* __restrict__ out)
{
    int b  = blockIdx.x;
    int oc = threadIdx.x;
    float s = 0.f;
    #pragma unroll
    for (int t = 0; t < NTILE; ++t) s += g_part[b][oc][t];
    out[b * C_ + oc] = tanhf(s * (1.0f / 4096.0f));
}

extern "C" void kernel_launch(void* const* d_in, const int* in_sizes, int n_in,
                              void* d_out, int out_size)
{
    const float* x    = (const float*)d_in[0];
    const float* w    = (const float*)d_in[1];
    const float* bias = (const float*)d_in[2];
    float* out = (float*)d_out;

    cudaFuncSetAttribute(fused_hmma_kernel,
                         cudaFuncAttributeMaxDynamicSharedMemorySize, SMEM_TOTAL);

    prep_wfragB<<<64, 256>>>(w);
    fused_hmma_kernel<<<dim3(NTILE, B_), 512, SMEM_TOTAL>>>(x, bias);
    finalize_kernel<<<B_, C_>>>(out);
}